// round 3
// baseline (speedup 1.0000x reference)
#include <cuda_runtime.h>
#include <cstdint>

// EmbeddingWithDropout:
//   out[t, :] = weight[x[t], :] * ((u[x[t]] >= 0.1f) ? (1.0f/0.9f) : 0.0f)
// x: int32 [131072], weight: f32 [100000,128], u: f32 [100000], out: f32 [131072,128]
//
// One warp per token. Each lane handles one float4 (4 floats) of the 128-wide row:
// 32 lanes x 16 B = 512 B per row, perfectly coalesced on both the gather read
// and the output write.

__global__ void __launch_bounds__(256)
embedding_dropout_kernel(const int* __restrict__ x,
                         const float4* __restrict__ weight,   // [vocab*32] float4
                         const float* __restrict__ u,         // [vocab]
                         float4* __restrict__ out,            // [n_tok*32] float4
                         int n_tok)
{
    const int gtid = blockIdx.x * blockDim.x + threadIdx.x;
    const int warp = gtid >> 5;
    const int lane = threadIdx.x & 31;
    if (warp >= n_tok) return;

    // Uniform (per-warp) loads: broadcast within the warp, served by one sector.
    const int row = __ldg(&x[warp]);
    const float uv = __ldg(&u[row]);
    const float keep = (uv >= 0.1f) ? (1.0f / 0.9f) : 0.0f;

    // Gather one float4 of the embedding row.
    float4 v = __ldg(&weight[(size_t)row * 32 + lane]);
    v.x *= keep;
    v.y *= keep;
    v.z *= keep;
    v.w *= keep;

    out[(size_t)warp * 32 + lane] = v;
}

extern "C" void kernel_launch(void* const* d_in, const int* in_sizes, int n_in,
                              void* d_out, int out_size)
{
    const int*    x      = (const int*)d_in[0];
    const float4* weight = (const float4*)d_in[1];
    const float*  u      = (const float*)d_in[2];
    float4*       out    = (float4*)d_out;

    const int n_tok = in_sizes[0];              // 64*2048 = 131072
    const int threads = 256;                    // 8 warps/block
    const int warps_per_block = threads / 32;
    const int blocks = (n_tok + warps_per_block - 1) / warps_per_block;

    embedding_dropout_kernel<<<blocks, threads>>>(x, weight, u, out, n_tok);
}

// round 4
// speedup vs baseline: 1.4858x; 1.4858x over previous
#include <cuda_runtime.h>
#include <cstdint>

// EmbeddingWithDropout:
//   out[t, :] = weight[x[t], :] * ((u[x[t]] >= 0.1f) ? (1.0f/0.9f) : 0.0f)
// x: int32 [131072], weight: f32 [100000,128], u: f32 [100000], out: f32 [131072,128]
//
// One warp handles T=8 consecutive tokens. Each lane owns one float4 (16 B) of the
// 128-wide row -> 32 lanes x 16 B = 512 B, coalesced on gather and store.
// The 8 index loads, 8 u loads, and 8 weight gathers are each issued as an
// independent batch (MLP=8) so the x->u->weight dependent chain is paid ~once,
// not 8 times. Streaming stores (__stcs) keep the 51 MB weight table L2-resident.

#define TOK_PER_WARP 8

__global__ void __launch_bounds__(256)
embedding_dropout_kernel(const int* __restrict__ x,
                         const float4* __restrict__ weight,   // [vocab*32] float4
                         const float* __restrict__ u,         // [vocab]
                         float4* __restrict__ out,            // [n_tok*32] float4
                         int n_tok)
{
    const int gtid = blockIdx.x * blockDim.x + threadIdx.x;
    const int warp = gtid >> 5;
    const int lane = threadIdx.x & 31;
    const int base = warp * TOK_PER_WARP;
    if (base >= n_tok) return;

    if (base + TOK_PER_WARP <= n_tok) {
        // ---- Fast path: full batch of 8 tokens ----
        int rows[TOK_PER_WARP];
        #pragma unroll
        for (int i = 0; i < TOK_PER_WARP; i++)
            rows[i] = __ldg(&x[base + i]);          // uniform broadcast loads

        float keep[TOK_PER_WARP];
        #pragma unroll
        for (int i = 0; i < TOK_PER_WARP; i++)
            keep[i] = (__ldg(&u[rows[i]]) >= 0.1f) ? (1.0f / 0.9f) : 0.0f;

        float4 v[TOK_PER_WARP];
        #pragma unroll
        for (int i = 0; i < TOK_PER_WARP; i++)      // 8 independent 16B gathers
            v[i] = __ldg(&weight[(size_t)rows[i] * 32 + lane]);

        #pragma unroll
        for (int i = 0; i < TOK_PER_WARP; i++) {
            v[i].x *= keep[i];
            v[i].y *= keep[i];
            v[i].z *= keep[i];
            v[i].w *= keep[i];
            __stcs(&out[(size_t)(base + i) * 32 + lane], v[i]);  // streaming store
        }
    } else {
        // ---- Tail path ----
        for (int i = 0; base + i < n_tok; i++) {
            const int row = __ldg(&x[base + i]);
            const float keep = (__ldg(&u[row]) >= 0.1f) ? (1.0f / 0.9f) : 0.0f;
            float4 v = __ldg(&weight[(size_t)row * 32 + lane]);
            v.x *= keep; v.y *= keep; v.z *= keep; v.w *= keep;
            __stcs(&out[(size_t)(base + i) * 32 + lane], v);
        }
    }
}

extern "C" void kernel_launch(void* const* d_in, const int* in_sizes, int n_in,
                              void* d_out, int out_size)
{
    const int*    x      = (const int*)d_in[0];
    const float4* weight = (const float4*)d_in[1];
    const float*  u      = (const float*)d_in[2];
    float4*       out    = (float4*)d_out;

    const int n_tok = in_sizes[0];                       // 131072
    const int threads = 256;                             // 8 warps/block
    const int tok_per_block = (threads / 32) * TOK_PER_WARP;  // 64
    const int blocks = (n_tok + tok_per_block - 1) / tok_per_block;

    embedding_dropout_kernel<<<blocks, threads>>>(x, weight, u, out, n_tok);
}